// round 14
// baseline (speedup 1.0000x reference)
#include <cuda_runtime.h>
#include <math.h>

#define NQ 20
#define NSTATE (1 << NQ)
#define GRID 256

typedef unsigned long long u64;

__device__ __align__(16) float2 d_state[NSTATE];
__device__ float d_partial[256];
__device__ unsigned bar_count = 0;
__device__ volatile unsigned bar_gen = 0;

// ---------- packed f32x2 helpers (R4, proven) ----------
__device__ __forceinline__ u64 pack2(float lo, float hi) {
    u64 d; asm("mov.b64 %0,{%1,%2};" : "=l"(d) : "f"(lo), "f"(hi)); return d;
}
__device__ __forceinline__ u64 swp(u64 x) {
    u64 d;
    asm("{\n\t.reg .b32 lo,hi;\n\tmov.b64 {lo,hi}, %1;\n\tmov.b64 %0,{hi,lo};\n\t}"
        : "=l"(d) : "l"(x));
    return d;
}
__device__ __forceinline__ u64 mul2(u64 a, u64 b) {
    u64 d; asm("mul.rn.f32x2 %0,%1,%2;" : "=l"(d) : "l"(a), "l"(b)); return d;
}
__device__ __forceinline__ u64 fma2(u64 a, u64 b, u64 c) {
    u64 d; asm("fma.rn.f32x2 %0,%1,%2,%3;" : "=l"(d) : "l"(a), "l"(b), "l"(c)); return d;
}
__device__ __forceinline__ float2 unp(u64 x) {
    float2 f; asm("mov.b64 {%0,%1}, %2;" : "=f"(f.x), "=f"(f.y) : "l"(x)); return f;
}
__device__ __forceinline__ float tanh_ap(float x) {
    float y; asm("tanh.approx.f32 %0,%1;" : "=f"(y) : "f"(x)); return y;
}

// ---------- L2-coherent loads (cross-phase reads MUST bypass L1) ----------
__device__ __forceinline__ u64 ldcg1(const u64* p) {
    u64 v; asm volatile("ld.global.cg.u64 %0,[%1];" : "=l"(v) : "l"(p)); return v;
}
__device__ __forceinline__ ulonglong2 ldcg2(const ulonglong2* p) {
    ulonglong2 v;
    asm volatile("ld.global.cg.v2.u64 {%0,%1},[%2];" : "=l"(v.x), "=l"(v.y) : "l"(p));
    return v;
}
__device__ __forceinline__ float ldcgf(const float* p) {
    float v; asm volatile("ld.global.cg.f32 %0,[%1];" : "=f"(v) : "l"(p)); return v;
}
__device__ __forceinline__ float4 ldcgf4(const float4* p) {
    float4 v;
    asm volatile("ld.global.cg.v4.f32 {%0,%1,%2,%3},[%4];"
                 : "=f"(v.x), "=f"(v.y), "=f"(v.z), "=f"(v.w) : "l"(p));
    return v;
}

// ---------- grid barrier (read gen BEFORE arrive; releaser resets count first) ----------
__device__ __forceinline__ void gbar(int tid) {
    __syncthreads();
    if (tid == 0) {
        unsigned g = bar_gen;
        __threadfence();
        if (atomicAdd(&bar_count, 1) == GRID - 1) {
            bar_count = 0;
            __threadfence();
            bar_gen = g + 1;
        } else {
            while (bar_gen == g) { }
        }
    }
    __syncthreads();
}

// gate packed layout: [axx, bxx, bxy, cxx, cxy, dxx, dxy] (stride 8 in smem)
__device__ __forceinline__ void make_gate_packed(const float* p, u64* dst) {
    float st, ct, sl, cl, sp, cp;
    sincosf(0.5f * p[0], &st, &ct);
    sincosf(p[2], &sl, &cl);
    sincosf(p[1], &sp, &cp);
    float bx = -cl * st, by = -sl * st;
    float cx = cp * st, cy = sp * st;
    float cpl = cp * cl - sp * sl, spl = sp * cl + cp * sl;
    float dx = cpl * ct, dy = spl * ct;
    dst[0] = pack2(ct, ct);
    dst[1] = pack2(bx, bx);
    dst[2] = pack2(-by, by);
    dst[3] = pack2(cx, cx);
    dst[4] = pack2(-cy, cy);
    dst[5] = pack2(dx, dx);
    dst[6] = pack2(-dy, dy);
}

// n0 = a*x0 + b*x1 (a real), n1 = c*x0 + d*x1, complex, packed re/im in u64
__device__ __forceinline__ void cpair(const u64* g, u64& x0, u64& x1) {
    u64 x0s = swp(x0), x1s = swp(x1);
    u64 n0 = mul2(g[0], x0);
    n0 = fma2(g[1], x1, n0);
    n0 = fma2(g[2], x1s, n0);
    u64 n1 = mul2(g[3], x0);
    n1 = fma2(g[4], x0s, n1);
    n1 = fma2(g[5], x1, n1);
    n1 = fma2(g[6], x1s, n1);
    x0 = n0; x1 = n1;
}

template <int J>
__device__ __forceinline__ void u3_reg(u64* v, const u64* sgate) {
    u64 g[7];
#pragma unroll
    for (int i = 0; i < 7; i++) g[i] = sgate[i];
#pragma unroll
    for (int p = 0; p < 8; p++) {
        int x = p & ((1 << J) - 1);
        int i0 = ((p ^ x) << 1) | x;
        cpair(g, v[i0], v[i0 | (1 << J)]);
    }
}

template <int C, int T>
__device__ __forceinline__ void cu3_reg(u64* v, const u64* sgate) {
    u64 g[7];
#pragma unroll
    for (int i = 0; i < 7; i++) g[i] = sgate[i];
    constexpr int B1 = (C < T) ? C : T;
    constexpr int B2 = (C < T) ? T : C;
#pragma unroll
    for (int p = 0; p < 4; p++) {
        int x = p & ((1 << B1) - 1);
        int t1 = ((p ^ x) << 1) | x;
        int y = t1 & ((1 << B2) - 1);
        int i0 = (((t1 ^ y) << 1) | y) | (1 << C);
        cpair(g, v[i0], v[i0 | (1 << T)]);
    }
}

// bank-conflict-avoiding swizzle for the 4096-entry u64 tile
__device__ __forceinline__ int sw(int i) { return i ^ ((i >> 4) & 15); }

// ============================================================================
// A body (R4 verbatim): enters w1 (v[r]: q0..3 = r, q4..11 = tid),
// exits w4 (v[r]: q8..11 = r, q0..7 = tid). U3 q0..11, CU3 (0,1)..(10,11).
// Caller guarantees tile is safe to write (sync before entry).
// ============================================================================
__device__ __forceinline__ void A_body(u64* v, u64* tile, const u64* sg, int tid) {
    u3_reg<0>(v, sg + 0 * 8); u3_reg<1>(v, sg + 1 * 8);
    u3_reg<2>(v, sg + 2 * 8); u3_reg<3>(v, sg + 3 * 8);
    cu3_reg<0, 1>(v, sg + 12 * 8); cu3_reg<1, 2>(v, sg + 13 * 8); cu3_reg<2, 3>(v, sg + 14 * 8);

    // T2 -> window {3,4,5,6}
#pragma unroll
    for (int r = 0; r < 16; r++) tile[sw((tid << 4) | r)] = v[r];
    __syncthreads();
#pragma unroll
    for (int r = 0; r < 16; r++) v[r] = tile[sw((tid & 7) | (r << 3) | ((tid >> 3) << 7))];
    u3_reg<1>(v, sg + 4 * 8); u3_reg<2>(v, sg + 5 * 8); u3_reg<3>(v, sg + 6 * 8);
    cu3_reg<0, 1>(v, sg + 15 * 8); cu3_reg<1, 2>(v, sg + 16 * 8); cu3_reg<2, 3>(v, sg + 17 * 8);

    // T3 -> window {6,7,8,9}
    __syncthreads();
#pragma unroll
    for (int r = 0; r < 16; r++) tile[sw((tid & 7) | (r << 3) | ((tid >> 3) << 7))] = v[r];
    __syncthreads();
#pragma unroll
    for (int r = 0; r < 16; r++) v[r] = tile[sw((tid & 63) | (r << 6) | ((tid >> 6) << 10))];
    u3_reg<1>(v, sg + 7 * 8); u3_reg<2>(v, sg + 8 * 8); u3_reg<3>(v, sg + 9 * 8);
    cu3_reg<0, 1>(v, sg + 18 * 8); cu3_reg<1, 2>(v, sg + 19 * 8); cu3_reg<2, 3>(v, sg + 20 * 8);

    // T4 -> window {8,9,10,11}
    __syncthreads();
#pragma unroll
    for (int r = 0; r < 16; r++) tile[sw((tid & 63) | (r << 6) | ((tid >> 6) << 10))] = v[r];
    __syncthreads();
#pragma unroll
    for (int r = 0; r < 16; r++) v[r] = tile[sw(tid | (r << 8))];
    u3_reg<2>(v, sg + 10 * 8); u3_reg<3>(v, sg + 11 * 8);
    cu3_reg<1, 2>(v, sg + 21 * 8); cu3_reg<2, 3>(v, sg + 22 * 8);
}

// ============================================================================
// B body (R4 verbatim): local l0..2 = q0..2, l3..11 = q11..19; cta = q3..10.
// Enters w1 (v[r]: l3..6 = r, l0..2 = tid&7, l7..11 = tid>>3); exits w3.
// U3 q12..19 (slots 0..7), CU3 (11+i,12+i) (slots 8..15), CU3 (19,0) (slot 16).
// ============================================================================
template <bool PRESYNC>
__device__ __forceinline__ void B_body(u64* v, u64* tile, const u64* sg, int tid) {
    u3_reg<1>(v, sg + 0 * 8); u3_reg<2>(v, sg + 1 * 8); u3_reg<3>(v, sg + 2 * 8);
    cu3_reg<0, 1>(v, sg + 8 * 8); cu3_reg<1, 2>(v, sg + 9 * 8); cu3_reg<2, 3>(v, sg + 10 * 8);

    // T2 -> window {l6..l9}
    if (PRESYNC) __syncthreads();
#pragma unroll
    for (int r = 0; r < 16; r++) tile[sw((tid & 7) | (r << 3) | ((tid >> 3) << 7))] = v[r];
    __syncthreads();
#pragma unroll
    for (int r = 0; r < 16; r++) v[r] = tile[sw((tid & 63) | (r << 6) | ((tid >> 6) << 10))];
    u3_reg<1>(v, sg + 3 * 8); u3_reg<2>(v, sg + 4 * 8); u3_reg<3>(v, sg + 5 * 8);
    cu3_reg<0, 1>(v, sg + 11 * 8); cu3_reg<1, 2>(v, sg + 12 * 8); cu3_reg<2, 3>(v, sg + 13 * 8);

    // T3 -> window {l9,l10,l11,l0}
    __syncthreads();
#pragma unroll
    for (int r = 0; r < 16; r++) tile[sw((tid & 63) | (r << 6) | ((tid >> 6) << 10))] = v[r];
    __syncthreads();
#pragma unroll
    for (int r = 0; r < 16; r++) v[r] = tile[sw((r >> 3) | (tid << 1) | ((r & 7) << 9))];
    u3_reg<1>(v, sg + 6 * 8); u3_reg<2>(v, sg + 7 * 8);
    cu3_reg<0, 1>(v, sg + 14 * 8); cu3_reg<1, 2>(v, sg + 15 * 8); cu3_reg<2, 3>(v, sg + 16 * 8);
}

// B final store: v[r]/v[r|8] adjacent in memory (q0 pair) -> 16B stores
__device__ __forceinline__ void B_store(const u64* v, u64* ds, int tid, int cta) {
#pragma unroll
    for (int r = 0; r < 8; r++) {
        int g = ((tid & 3) << 1) | (cta << 3) | (((tid >> 2) | (r << 6)) << 11);
        ulonglong2 val; val.x = v[r]; val.y = v[r | 8];
        *reinterpret_cast<ulonglong2*>(ds + g) = val;
    }
}

// ============================================================================
// Single persistent kernel: AB0 | A1 | B1 | A2 | B2+finalize | mean+subtract,
// separated by grid barriers. 256 CTAs co-resident (2/SM forced).
// ============================================================================
__global__ void __launch_bounds__(256, 2) qc_persist(const float* __restrict__ u3p,
                                                     const float* __restrict__ cu3p,
                                                     float* __restrict__ out) {
    __shared__ u64 tile[4096];
    __shared__ u64 sg[320];
    __shared__ float red[8];
    __shared__ float meanv;
    int tid = threadIdx.x, cta = blockIdx.x;
    u64* ds = (u64*)d_state;
    u64 v[16];

    // ================= phase 0: fused A(0)+B(0) =================
    if (tid < 40) {
        const float* p;
        if (tid < 12)      p = u3p + tid * 3;
        else if (tid < 23) p = cu3p + (tid - 12) * 3;
        else {
            int t = tid - 23;
            if (t < 8)       p = u3p + (12 + t) * 3;
            else if (t < 16) p = cu3p + (11 + (t - 8)) * 3;
            else             p = cu3p + 19 * 3;
        }
        make_gate_packed(p, sg + tid * 8);
    }
#pragma unroll
    for (int r = 0; r < 16; r++) v[r] = 0ull;
    if (tid == 0) v[0] = pack2(1.f, 0.f);  // |0..0> in w1 layout
    __syncthreads();

    A_body(v, tile, sg, tid);

    __syncthreads();
#pragma unroll
    for (int r = 0; r < 16; r++) tile[sw((r << 8) | tid)] = v[r];
    __syncthreads();

    // B w1 nonzero inputs: q0..2 = tid (tid<8), q3..10 = cta, q11 = r bit0
    {
        u64 a0 = 0ull, a1 = 0ull;
        if (tid < 8) {
            int i0 = tid | (cta << 3);
            a0 = tile[sw(i0)];
            a1 = tile[sw(i0 | 2048)];
        }
#pragma unroll
        for (int r = 0; r < 16; r++) v[r] = 0ull;
        v[0] = a0; v[1] = a1;
    }
    B_body<true>(v, tile, sg + 23 * 8, tid);
    B_store(v, ds, tid, cta);

    gbar(tid);

    // ================= blocks k = 1, 2 =================
#pragma unroll 1
    for (int k = 1; k <= 2; k++) {
        // ---- A phase: load w1 (contiguous 128B/thread), gates, store canonical ----
        if (tid < 23) {
            const float* p = (tid < 12) ? u3p + (k * NQ + tid) * 3
                                        : cu3p + (k * NQ + (tid - 12)) * 3;
            make_gate_packed(p, sg + tid * 8);
        }
        {
            u64* gp = ds + ((size_t)cta << 12);
            const ulonglong2* g2 = (const ulonglong2*)gp;
#pragma unroll
            for (int j = 0; j < 8; j++) {  // v[r] = gp[(tid<<4)|r]
                ulonglong2 val = ldcg2(g2 + tid * 8 + j);
                v[2 * j] = val.x; v[2 * j + 1] = val.y;
            }
        }
        __syncthreads();

        A_body(v, tile, sg, tid);

        {
            u64* gp = ds + ((size_t)cta << 12);
#pragma unroll
            for (int r = 0; r < 16; r++) gp[(r << 8) | tid] = v[r];
        }
        gbar(tid);

        // ---- B phase ----
        if (tid < 17) {
            const float* p;
            if (tid < 8)       p = u3p + (k * NQ + 12 + tid) * 3;
            else if (tid < 16) p = cu3p + (k * NQ + 11 + (tid - 8)) * 3;
            else               p = cu3p + (k * NQ + 19) * 3;
            make_gate_packed(p, sg + tid * 8);
        }
        {
            int b0 = (tid & 7) | (cta << 3) | ((tid >> 3) << 15);
#pragma unroll
            for (int r = 0; r < 16; r++) v[r] = ldcg1(ds + (b0 | (r << 11)));
        }
        __syncthreads();

        B_body<false>(v, tile, sg, tid);

        if (k == 1) {
            B_store(v, ds, tid, cta);
        } else {
            // fused finalize: xv = (0.8*tanh(0.1*2^19*|psi|^2))^0.3 at bit-reversed idx
            float sum = 0.f;
#pragma unroll
            for (int h = 0; h < 2; h++) {
                float xv[8];
#pragma unroll
                for (int rr = 0; rr < 8; rr++) {
                    float2 a = unp(v[rr | (h << 3)]);
                    float pr = a.x * a.x + a.y * a.y;
                    float t = 0.8f * tanh_ap(52428.8f * pr);  // gamma * 2^19
                    float x = __powf(t, 0.3f);
                    int j = ((rr & 1) << 2) | (rr & 2) | (rr >> 2);  // brev3
                    xv[j] = x;
                    sum += x;
                }
                int g0 = h | ((tid & 3) << 1) | (cta << 3) | ((tid >> 2) << 11);
                int obase = (int)(__brev((unsigned)g0) >> 12);  // low 3 bits zero
                float4* o4 = (float4*)(out + obase);
                o4[0] = make_float4(xv[0], xv[1], xv[2], xv[3]);
                o4[1] = make_float4(xv[4], xv[5], xv[6], xv[7]);
            }
            for (int o = 16; o > 0; o >>= 1) sum += __shfl_down_sync(0xffffffffu, sum, o);
            if ((tid & 31) == 0) red[tid >> 5] = sum;
            __syncthreads();
            if (tid == 0) {
                float s = 0.f;
#pragma unroll
                for (int w = 0; w < 8; w++) s += red[w];
                d_partial[cta] = s;
            }
        }
        gbar(tid);
    }

    // ================= mean + subtract =================
    {
        float s = ldcgf(d_partial + tid);
        for (int o = 16; o > 0; o >>= 1) s += __shfl_down_sync(0xffffffffu, s, o);
        if ((tid & 31) == 0) red[tid >> 5] = s;
        __syncthreads();
        if (tid == 0) {
            float t = 0.f;
#pragma unroll
            for (int w = 0; w < 8; w++) t += red[w];
            meanv = t * (1.0f / 1048576.0f);
        }
        __syncthreads();
        float m = meanv;
        float4* o4 = (float4*)out;
#pragma unroll
        for (int j = 0; j < 4; j++) {
            int i = cta * 1024 + j * 256 + tid;
            float4 x = ldcgf4(o4 + i);
            x.x -= m; x.y -= m; x.z -= m; x.w -= m;
            o4[i] = x;
        }
    }
}

extern "C" void kernel_launch(void* const* d_in, const int* in_sizes, int n_in,
                              void* d_out, int out_size) {
    const float* u3p = (const float*)d_in[0];   // (3, 20, 3)
    const float* cu3p = (const float*)d_in[1];  // (3, 20, 3)
    float* out = (float*)d_out;                 // 2^20 floats

    qc_persist<<<GRID, 256>>>(u3p, cu3p, out);
}

// round 17
// speedup vs baseline: 1.0281x; 1.0281x over previous
#include <cuda_runtime.h>
#include <math.h>

#define NQ 20
typedef unsigned long long u64;

__device__ __align__(16) float2 d_state[1 << 20];
__device__ float d_partial[256];

// ---------- packed f32x2 helpers (R4, proven) ----------
__device__ __forceinline__ u64 pack2(float lo, float hi) {
    u64 d; asm("mov.b64 %0,{%1,%2};" : "=l"(d) : "f"(lo), "f"(hi)); return d;
}
__device__ __forceinline__ u64 swp(u64 x) {
    u64 d;
    asm("{\n\t.reg .b32 lo,hi;\n\tmov.b64 {lo,hi}, %1;\n\tmov.b64 %0,{hi,lo};\n\t}"
        : "=l"(d) : "l"(x));
    return d;
}
__device__ __forceinline__ u64 mul2(u64 a, u64 b) {
    u64 d; asm("mul.rn.f32x2 %0,%1,%2;" : "=l"(d) : "l"(a), "l"(b)); return d;
}
__device__ __forceinline__ u64 fma2(u64 a, u64 b, u64 c) {
    u64 d; asm("fma.rn.f32x2 %0,%1,%2,%3;" : "=l"(d) : "l"(a), "l"(b), "l"(c)); return d;
}
__device__ __forceinline__ float2 unp(u64 x) {
    float2 f; asm("mov.b64 {%0,%1}, %2;" : "=f"(f.x), "=f"(f.y) : "l"(x)); return f;
}
__device__ __forceinline__ float tanh_ap(float x) {
    float y; asm("tanh.approx.f32 %0,%1;" : "=f"(y) : "f"(x)); return y;
}

// gate packed layout: [axx, bxx, bxy, cxx, cxy, dxx, dxy] (stride 8 in smem)
__device__ __forceinline__ void make_gate_packed(const float* p, u64* dst) {
    float st, ct, sl, cl, sp, cp;
    sincosf(0.5f * p[0], &st, &ct);
    sincosf(p[2], &sl, &cl);
    sincosf(p[1], &sp, &cp);
    float bx = -cl * st, by = -sl * st;
    float cx = cp * st, cy = sp * st;
    float cpl = cp * cl - sp * sl, spl = sp * cl + cp * sl;
    float dx = cpl * ct, dy = spl * ct;
    dst[0] = pack2(ct, ct);
    dst[1] = pack2(bx, bx);
    dst[2] = pack2(-by, by);
    dst[3] = pack2(cx, cx);
    dst[4] = pack2(-cy, cy);
    dst[5] = pack2(dx, dx);
    dst[6] = pack2(-dy, dy);
}

// n0 = a*x0 + b*x1 (a real), n1 = c*x0 + d*x1, complex, packed re/im in u64
__device__ __forceinline__ void cpair(const u64* g, u64& x0, u64& x1) {
    u64 x0s = swp(x0), x1s = swp(x1);
    u64 n0 = mul2(g[0], x0);
    n0 = fma2(g[1], x1, n0);
    n0 = fma2(g[2], x1s, n0);
    u64 n1 = mul2(g[3], x0);
    n1 = fma2(g[4], x0s, n1);
    n1 = fma2(g[5], x1, n1);
    n1 = fma2(g[6], x1s, n1);
    x0 = n0; x1 = n1;
}

// ---------- 5-bit register window ops (32 amps/thread) ----------
// U3 on reg bit J (16 pairs)
template <int J>
__device__ __forceinline__ void u3_reg(u64* v, const u64* sgate) {
    u64 g[7];
#pragma unroll
    for (int i = 0; i < 7; i++) g[i] = sgate[i];
#pragma unroll
    for (int p = 0; p < 16; p++) {
        int x = p & ((1 << J) - 1);
        int i0 = ((p ^ x) << 1) | x;
        cpair(g, v[i0], v[i0 | (1 << J)]);
    }
}

// CU3: ctrl reg bit C = 1, target reg bit T (8 pairs)
template <int C, int T>
__device__ __forceinline__ void cu3_reg(u64* v, const u64* sgate) {
    u64 g[7];
#pragma unroll
    for (int i = 0; i < 7; i++) g[i] = sgate[i];
    constexpr int B1 = (C < T) ? C : T;
    constexpr int B2 = (C < T) ? T : C;
#pragma unroll
    for (int p = 0; p < 8; p++) {
        int x = p & ((1 << B1) - 1);
        int t1 = ((p ^ x) << 1) | x;
        int y = t1 & ((1 << B2) - 1);
        int i0 = (((t1 ^ y) << 1) | y) | (1 << C);
        cpair(g, v[i0], v[i0 | (1 << T)]);
    }
}

// Per-transpose swizzles for the 4096-u64 tile (each pattern verified
// conflict-free per half-warp):
__device__ __forceinline__ int swa(int i) { return i ^ ((i >> 5) & 31); }
__device__ __forceinline__ int swb(int i) { return i ^ ((i >> 4) & 15); }

// ============================================================================
// K1 body: tile = q0..11 (12 bits), cta = q12..19. 128 threads, 32 amps.
// Windows: W1 reg=q0..4, W2 reg=q4..8, W3 reg=q7..11. 2 transposes, 3 syncs.
// Gates: U3 q0..11 (slots 0..11), CU3 (q,q+1) q=0..10 (slots 12..22).
// Enters W1 layout (l = r | t<<5); exits W3 layout (l = t | r<<7 = canonical).
// ============================================================================
__device__ __forceinline__ void K1_body(u64* v, u64* tile, const u64* sg, int t) {
    // W1: U3 q0..4, CU3 (0,1)..(3,4)
    u3_reg<0>(v, sg + 0 * 8); u3_reg<1>(v, sg + 1 * 8); u3_reg<2>(v, sg + 2 * 8);
    u3_reg<3>(v, sg + 3 * 8); u3_reg<4>(v, sg + 4 * 8);
    cu3_reg<0, 1>(v, sg + 12 * 8); cu3_reg<1, 2>(v, sg + 13 * 8);
    cu3_reg<2, 3>(v, sg + 14 * 8); cu3_reg<3, 4>(v, sg + 15 * 8);

    // T2 -> W2 (reg = q4..8; t: low4 = q0..3, high3 = q9..11)
#pragma unroll
    for (int r = 0; r < 32; r++) tile[swa(r | (t << 5))] = v[r];
    __syncthreads();
#pragma unroll
    for (int r = 0; r < 32; r++) v[r] = tile[swa((t & 15) | (r << 4) | ((t >> 4) << 9))];
    u3_reg<1>(v, sg + 5 * 8); u3_reg<2>(v, sg + 6 * 8);
    u3_reg<3>(v, sg + 7 * 8); u3_reg<4>(v, sg + 8 * 8);
    cu3_reg<0, 1>(v, sg + 16 * 8); cu3_reg<1, 2>(v, sg + 17 * 8);
    cu3_reg<2, 3>(v, sg + 18 * 8); cu3_reg<3, 4>(v, sg + 19 * 8);

    // T3 -> W3 (reg = q7..11; t = q0..6)
    __syncthreads();
#pragma unroll
    for (int r = 0; r < 32; r++) tile[swa((t & 15) | (r << 4) | ((t >> 4) << 9))] = v[r];
    __syncthreads();
#pragma unroll
    for (int r = 0; r < 32; r++) v[r] = tile[swa(t | (r << 7))];
    u3_reg<2>(v, sg + 9 * 8); u3_reg<3>(v, sg + 10 * 8); u3_reg<4>(v, sg + 11 * 8);
    cu3_reg<1, 2>(v, sg + 20 * 8); cu3_reg<2, 3>(v, sg + 21 * 8); cu3_reg<3, 4>(v, sg + 22 * 8);
}

// ============================================================================
// K2 body: local l0..2 = q0..2, l3..11 = q11..19; cta = q3..10.
// W1 reg=l3..7 (q11..15), t=(l0..2, l8..11); W2 reg=l7..11 (q15..19), t=l0..6;
// W3 reg: r0..3 = l8..11 (q16..19), r4 = l0 (q0); t = l1..7.
// Gates: U3 q12..19 (slots 0..7), CU3 (11,12)..(18,19) (8..15), CU3 (19,0) (16).
// ============================================================================
template <bool PRESYNC>
__device__ __forceinline__ void K2_body(u64* v, u64* tile, const u64* sg, int t) {
    // W1: U3 q12..15, CU3 (11,12)..(14,15)
    u3_reg<1>(v, sg + 0 * 8); u3_reg<2>(v, sg + 1 * 8);
    u3_reg<3>(v, sg + 2 * 8); u3_reg<4>(v, sg + 3 * 8);
    cu3_reg<0, 1>(v, sg + 8 * 8); cu3_reg<1, 2>(v, sg + 9 * 8);
    cu3_reg<2, 3>(v, sg + 10 * 8); cu3_reg<3, 4>(v, sg + 11 * 8);

    // T2 -> W2
    if (PRESYNC) __syncthreads();
#pragma unroll
    for (int r = 0; r < 32; r++) tile[swa((t & 7) | (r << 3) | ((t >> 3) << 8))] = v[r];
    __syncthreads();
#pragma unroll
    for (int r = 0; r < 32; r++) v[r] = tile[swa(t | (r << 7))];
    u3_reg<1>(v, sg + 4 * 8); u3_reg<2>(v, sg + 5 * 8);
    u3_reg<3>(v, sg + 6 * 8); u3_reg<4>(v, sg + 7 * 8);
    cu3_reg<0, 1>(v, sg + 12 * 8); cu3_reg<1, 2>(v, sg + 13 * 8);
    cu3_reg<2, 3>(v, sg + 14 * 8); cu3_reg<3, 4>(v, sg + 15 * 8);

    // T3 -> W3 (swb for conflict-freedom of the W3 load pattern)
    __syncthreads();
#pragma unroll
    for (int r = 0; r < 32; r++) tile[swb(t | (r << 7))] = v[r];
    __syncthreads();
#pragma unroll
    for (int r = 0; r < 32; r++) v[r] = tile[swb((r >> 4) | (t << 1) | ((r & 15) << 8))];
    cu3_reg<3, 4>(v, sg + 16 * 8);  // CU3(19,0): ctrl q19=r3, tgt q0=r4
}

// K2 exit store (canonical): q0 = r4 pair -> 16B stores, 64B-coalesced groups
__device__ __forceinline__ void K2_store(const u64* v, u64* ds, int t, int cta) {
#pragma unroll
    for (int r = 0; r < 16; r++) {
        int a = ((t & 3) << 1) | (cta << 3) | ((t >> 2) << 11) | (r << 16);
        ulonglong2 x; x.x = v[r]; x.y = v[r | 16];
        *reinterpret_cast<ulonglong2*>(ds + a) = x;
    }
}

// gate prep (one thread per slot)
__device__ __forceinline__ void prep_K1(u64* sg, const float* u3p, const float* cu3p,
                                        int k, int tid) {
    if (tid < 23) {
        const float* p = (tid < 12) ? u3p + (k * NQ + tid) * 3
                                    : cu3p + (k * NQ + tid - 12) * 3;
        make_gate_packed(p, sg + tid * 8);
    }
}
__device__ __forceinline__ void prep_K2(u64* sg, const float* u3p, const float* cu3p,
                                        int k, int tid) {
    if (tid < 17) {
        const float* p;
        if (tid < 8)       p = u3p + (k * NQ + 12 + tid) * 3;
        else if (tid < 16) p = cu3p + (k * NQ + 11 + (tid - 8)) * 3;
        else               p = cu3p + (k * NQ + 19) * 3;
        make_gate_packed(p, sg + tid * 8);
    }
}

// ============================================================================
// Fused K1(0)+K2(0): after K1(0) from |0..0>, nonzero amps have q12..19 = 0.
// Every CTA computes the 4096-amp tile redundantly, extracts its two inputs
// (q11 free), runs K2(0).
// ============================================================================
__global__ void __launch_bounds__(128) gate_AB0(const float* __restrict__ u3p,
                                                const float* __restrict__ cu3p) {
    __shared__ u64 tile[4096];
    __shared__ u64 sgA[184];
    __shared__ u64 sgB[136];
    int t = threadIdx.x, cta = blockIdx.x;

    prep_K1(sgA, u3p, cu3p, 0, t);
    if (t >= 32 && t < 49) prep_K2(sgB, u3p, cu3p, 0, t - 32);

    u64 v[32];
#pragma unroll
    for (int r = 0; r < 32; r++) v[r] = 0ull;
    if (t == 0) v[0] = pack2(1.f, 0.f);  // |0..0> in K1-W1 layout
    __syncthreads();

    K1_body(v, tile, sgA, t);

    // publish (W3 layout IS canonical; same slots each thread read -> no hazard)
#pragma unroll
    for (int r = 0; r < 32; r++) tile[swa(t | (r << 7))] = v[r];
    __syncthreads();

    // K2-W1 nonzero inputs: t3..6 = q16..19 = 0 (t<8); r in {0,1} (q11 free)
    u64 a0 = 0ull, a1 = 0ull;
    if (t < 8) {
        int b = t | (cta << 3);
        a0 = tile[swa(b)];          // q11 = 0
        a1 = tile[swa(b | 2048)];   // q11 = 1
    }
#pragma unroll
    for (int r = 0; r < 32; r++) v[r] = 0ull;
    v[0] = a0; v[1] = a1;

    K2_body<true>(v, tile, sgB, t);
    K2_store(v, (u64*)d_state, t, cta);
}

// ============================================================================
// K1 (k=1,2): load W1 (256B contiguous/thread), gates, store canonical.
// ============================================================================
__global__ void __launch_bounds__(128) gate_K1(const float* __restrict__ u3p,
                                               const float* __restrict__ cu3p, int k) {
    __shared__ u64 tile[4096];
    __shared__ u64 sg[184];
    int t = threadIdx.x, cta = blockIdx.x;
    u64* gp = (u64*)d_state + ((size_t)cta << 12);

    prep_K1(sg, u3p, cu3p, k, t);

    u64 v[32];
    const ulonglong2* g2 = (const ulonglong2*)(gp + (t << 5));
#pragma unroll
    for (int j = 0; j < 16; j++) {  // v[r] = gp[(t<<5)|r]
        ulonglong2 x = g2[j];
        v[2 * j] = x.x; v[2 * j + 1] = x.y;
    }
    __syncthreads();

    K1_body(v, tile, sg, t);

#pragma unroll
    for (int r = 0; r < 32; r++) gp[(r << 7) | t] = v[r];  // canonical, coalesced
}

// ============================================================================
// K2 (k=1,2): load W1 (64B-granular), gates; store canonical or fused finalize.
// ============================================================================
template <bool LAST>
__global__ void __launch_bounds__(128) gate_K2(const float* __restrict__ u3p,
                                               const float* __restrict__ cu3p, int k,
                                               float* __restrict__ out) {
    __shared__ u64 tile[4096];
    __shared__ u64 sg[136];
    int t = threadIdx.x, cta = blockIdx.x;

    prep_K2(sg, u3p, cu3p, k, t);

    u64* ds = (u64*)d_state;
    int b0 = (t & 7) | (cta << 3) | ((t >> 3) << 16);
    u64 v[32];
#pragma unroll
    for (int r = 0; r < 32; r++) v[r] = ds[b0 | (r << 11)];  // q11..15 = r
    __syncthreads();

    K2_body<false>(v, tile, sg, t);

    if (!LAST) {
        K2_store(v, ds, t, cta);
    } else {
        // W3 regs: q0 = r4, q1,q2 = t0,t1, q3..10 = cta, q11..15 = t2..6, q16..19 = r0..3
        // out = brev20(g): each thread writes two contiguous 16-float (64B) runs
        float sum = 0.f;
        int base = ((t & 1) << 18) | (((t >> 1) & 1) << 17) |
                   ((int)(__brev((unsigned)cta) >> 24) << 9) |
                   ((int)(__brev((unsigned)(t >> 2)) >> 27) << 4);
#pragma unroll
        for (int h = 0; h < 2; h++) {
            float arr[16];
#pragma unroll
            for (int j = 0; j < 16; j++) {
                float2 a = unp(v[j | (h << 4)]);
                float pr = a.x * a.x + a.y * a.y;
                float tt = 0.8f * tanh_ap(52428.8f * pr);  // gamma * 2^19
                float x = __powf(tt, 0.3f);
                arr[(int)(__brev((unsigned)j) >> 28)] = x;  // rev4(j)
                sum += x;
            }
            float4* o4 = (float4*)(out + (base | (h << 19)));
            o4[0] = make_float4(arr[0], arr[1], arr[2], arr[3]);
            o4[1] = make_float4(arr[4], arr[5], arr[6], arr[7]);
            o4[2] = make_float4(arr[8], arr[9], arr[10], arr[11]);
            o4[3] = make_float4(arr[12], arr[13], arr[14], arr[15]);
        }
        for (int o = 16; o > 0; o >>= 1) sum += __shfl_down_sync(0xffffffffu, sum, o);
        __shared__ float red[4];
        if ((t & 31) == 0) red[t >> 5] = sum;
        __syncthreads();
        if (t == 0) d_partial[cta] = red[0] + red[1] + red[2] + red[3];
    }
}

// mean from 256 partials (redundant per CTA, L2-hot), then subtract
__global__ void __launch_bounds__(256) finalize_sub(float4* __restrict__ o4) {
    int tid = threadIdx.x;
    int i = blockIdx.x * 256 + tid;
    float4 x = o4[i];

    float s = d_partial[tid];
    for (int o = 16; o > 0; o >>= 1) s += __shfl_down_sync(0xffffffffu, s, o);
    __shared__ float red[8];
    __shared__ float mean;
    if ((tid & 31) == 0) red[tid >> 5] = s;
    __syncthreads();
    if (tid == 0) {
        float tt = 0.f;
#pragma unroll
        for (int w = 0; w < 8; w++) tt += red[w];
        mean = tt * (1.0f / 1048576.0f);
    }
    __syncthreads();
    float m = mean;
    x.x -= m; x.y -= m; x.z -= m; x.w -= m;
    o4[i] = x;
}

extern "C" void kernel_launch(void* const* d_in, const int* in_sizes, int n_in,
                              void* d_out, int out_size) {
    const float* u3p = (const float*)d_in[0];   // (3, 20, 3)
    const float* cu3p = (const float*)d_in[1];  // (3, 20, 3)
    float* out = (float*)d_out;                 // 2^20 floats

    gate_AB0<<<256, 128>>>(u3p, cu3p);
    gate_K1<<<256, 128>>>(u3p, cu3p, 1);
    gate_K2<false><<<256, 128>>>(u3p, cu3p, 1, out);
    gate_K1<<<256, 128>>>(u3p, cu3p, 2);
    gate_K2<true><<<256, 128>>>(u3p, cu3p, 2, out);
    finalize_sub<<<1024, 256>>>((float4*)out);
}